// round 1
// baseline (speedup 1.0000x reference)
#include <cuda_runtime.h>
#include <cuda_bf16.h>
#include <cstdint>

// Problem constants (fixed by the dataset problem)
#define IN_F   4096
#define OUT_F  4096
#define RANK   8
#define MTOT   8192          // 4 * 2048 rows of x
#define KDIM   4096
#define NDIM   4096

// Quantized operand scratch (integer codes in [-8,7] stored as bf16 -> exact)
__device__ __nv_bfloat16 g_xq[(size_t)MTOT * KDIM];   // 64 MB
__device__ __nv_bfloat16 g_wq[(size_t)NDIM * KDIM];   // 32 MB

__device__ __forceinline__ float qclip(float v) {
    return fminf(7.0f, fmaxf(-8.0f, rintf(v)));
}

// ---------------------------------------------------------------------------
// Kernel 1: activation quantization  qx = clip(round(x / ts))
// ---------------------------------------------------------------------------
__global__ void quant_x_kernel(const float* __restrict__ x,
                               const float* __restrict__ tscales,
                               const int*   __restrict__ step) {
    int i = blockIdx.x * blockDim.x + threadIdx.x;   // float4 index
    const int n4 = (MTOT * KDIM) / 4;
    if (i >= n4) return;
    float ts = tscales[*step];
    float4 v = reinterpret_cast<const float4*>(x)[i];
    float q0 = qclip(v.x / ts);
    float q1 = qclip(v.y / ts);
    float q2 = qclip(v.z / ts);
    float q3 = qclip(v.w / ts);
    __nv_bfloat162 p0 = __floats2bfloat162_rn(q0, q1);
    __nv_bfloat162 p1 = __floats2bfloat162_rn(q2, q3);
    reinterpret_cast<__nv_bfloat162*>(g_xq)[2 * i]     = p0;
    reinterpret_cast<__nv_bfloat162*>(g_xq)[2 * i + 1] = p1;
}

// ---------------------------------------------------------------------------
// Kernel 2: weight merge + quantization
//   merged[o,i] = W[o,i] + sum_r B[o,r]*A[r,i];  qw = clip(round(merged/scale_o))
// One block per output row o; 1024 threads, one float4 of columns each.
// ---------------------------------------------------------------------------
__global__ void quant_w_kernel(const float* __restrict__ W,
                               const float* __restrict__ lA,
                               const float* __restrict__ lB,
                               const float* __restrict__ wscale) {
    int o  = blockIdx.x;
    int i4 = threadIdx.x;            // 0..1023 -> columns i4*4 .. i4*4+3
    float b[RANK];
#pragma unroll
    for (int r = 0; r < RANK; r++) b[r] = lB[o * RANK + r];
    float s = wscale[o];
    float4 w = reinterpret_cast<const float4*>(W + (size_t)o * IN_F)[i4];
    float m0 = w.x, m1 = w.y, m2 = w.z, m3 = w.w;
#pragma unroll
    for (int r = 0; r < RANK; r++) {
        float4 a = reinterpret_cast<const float4*>(lA + (size_t)r * IN_F)[i4];
        m0 += b[r] * a.x; m1 += b[r] * a.y; m2 += b[r] * a.z; m3 += b[r] * a.w;
    }
    float q0 = qclip(m0 / s), q1 = qclip(m1 / s);
    float q2 = qclip(m2 / s), q3 = qclip(m3 / s);
    __nv_bfloat162 p0 = __floats2bfloat162_rn(q0, q1);
    __nv_bfloat162 p1 = __floats2bfloat162_rn(q2, q3);
    size_t base = ((size_t)o * IN_F) / 2 + (size_t)i4 * 2;
    reinterpret_cast<__nv_bfloat162*>(g_wq)[base]     = p0;
    reinterpret_cast<__nv_bfloat162*>(g_wq)[base + 1] = p1;
}

// ---------------------------------------------------------------------------
// Kernel 3: bf16 GEMM  out[m,o] = (sum_k qx[m,k]*qw[o,k]) * ts*scale[o] + bias[o]
// 128x128x32 tiles, 2-stage cp.async pipeline, mma.sync m16n8k16.
// 256 threads = 8 warps in a 4(M) x 2(N) grid; warp tile 32x64.
// ---------------------------------------------------------------------------
#define BM 128
#define BN 128
#define BK 32
#define KTILES (KDIM / BK)   // 128

__device__ __forceinline__ uint32_t swz(int row, int chunk) {
    // row of 64B = 4 chunks of 16B; XOR swizzle -> conflict-free ldmatrix/STS
    return (uint32_t)(row * 64 + ((chunk ^ ((row >> 1) & 3)) << 4));
}

__device__ __forceinline__ void cp_async16(uint32_t saddr, const void* gaddr) {
    asm volatile("cp.async.cg.shared.global [%0], [%1], 16;\n"
                 :: "r"(saddr), "l"(gaddr));
}

__global__ __launch_bounds__(256) void gemm_kernel(
    float* __restrict__ out,
    const float* __restrict__ wscale,
    const float* __restrict__ bias,
    const float* __restrict__ tscales,
    const int*  __restrict__ step)
{
    __shared__ __align__(128) unsigned char smem[2 * (8192 + 8192)]; // 32 KB
    const int tid   = threadIdx.x;
    const int lane  = tid & 31;
    const int warp  = tid >> 5;
    const int warpM = warp & 3;      // 0..3
    const int warpN = warp >> 2;     // 0..1
    const int bm0 = blockIdx.y * BM;
    const int bn0 = blockIdx.x * BN;

    const uint32_t sbase = (uint32_t)__cvta_generic_to_shared(smem);
    const uint32_t sA = sbase;           // 2 stages x 8KB
    const uint32_t sB = sbase + 16384;   // 2 stages x 8KB

    float acc[2][8][4];
#pragma unroll
    for (int mi = 0; mi < 2; mi++)
#pragma unroll
        for (int ni = 0; ni < 8; ni++)
#pragma unroll
            for (int c = 0; c < 4; c++) acc[mi][ni][c] = 0.0f;

    // ------- tile loader: 512 16B chunks per operand, 2 per thread -------
    auto load_tile = [&](int s, int kt) {
        const int k0 = kt * BK;
#pragma unroll
        for (int p = 0; p < 2; p++) {
            int ci  = tid + p * 256;
            int row = ci >> 2;
            int c   = ci & 3;
            const __nv_bfloat16* ga = &g_xq[(size_t)(bm0 + row) * KDIM + k0 + c * 8];
            cp_async16(sA + s * 8192 + swz(row, c), ga);
            const __nv_bfloat16* gb = &g_wq[(size_t)(bn0 + row) * KDIM + k0 + c * 8];
            cp_async16(sB + s * 8192 + swz(row, c), gb);
        }
        asm volatile("cp.async.commit_group;\n" ::);
    };

    load_tile(0, 0);

    const int q = lane >> 3;     // ldmatrix quadrant
    const int w = lane & 7;

    for (int kt = 0; kt < KTILES; ++kt) {
        const int s = kt & 1;
        if (kt < KTILES - 1) {
            load_tile(s ^ 1, kt + 1);
            asm volatile("cp.async.wait_group 1;\n" ::);
        } else {
            asm volatile("cp.async.wait_group 0;\n" ::);
        }
        __syncthreads();

#pragma unroll
        for (int kk = 0; kk < 2; kk++) {
            // A fragments: 2 m-tiles of 16x16
            uint32_t aF[2][4];
#pragma unroll
            for (int mi = 0; mi < 2; mi++) {
                int r  = warpM * 32 + mi * 16 + w + 8 * (q & 1);
                int ch = 2 * kk + (q >> 1);
                uint32_t addr = sA + s * 8192 + swz(r, ch);
                asm volatile(
                    "ldmatrix.sync.aligned.m8n8.x4.shared.b16 {%0,%1,%2,%3}, [%4];\n"
                    : "=r"(aF[mi][0]), "=r"(aF[mi][1]), "=r"(aF[mi][2]), "=r"(aF[mi][3])
                    : "r"(addr));
            }
            // B fragments: 8 n-tiles of 8x16, loaded as 4 x ldmatrix.x4 (16 rows each)
            uint32_t bF[8][2];
#pragma unroll
            for (int j = 0; j < 4; j++) {
                int r  = warpN * 64 + j * 16 + w + 8 * (q & 1);
                int ch = 2 * kk + (q >> 1);
                uint32_t addr = sB + s * 8192 + swz(r, ch);
                uint32_t t0, t1, t2, t3;
                asm volatile(
                    "ldmatrix.sync.aligned.m8n8.x4.shared.b16 {%0,%1,%2,%3}, [%4];\n"
                    : "=r"(t0), "=r"(t1), "=r"(t2), "=r"(t3)
                    : "r"(addr));
                bF[2 * j][0] = t0; bF[2 * j + 1][0] = t1;
                bF[2 * j][1] = t2; bF[2 * j + 1][1] = t3;
            }
#pragma unroll
            for (int mi = 0; mi < 2; mi++)
#pragma unroll
                for (int ni = 0; ni < 8; ni++) {
                    asm volatile(
                        "mma.sync.aligned.m16n8k16.row.col.f32.bf16.bf16.f32 "
                        "{%0,%1,%2,%3}, {%4,%5,%6,%7}, {%8,%9}, {%0,%1,%2,%3};\n"
                        : "+f"(acc[mi][ni][0]), "+f"(acc[mi][ni][1]),
                          "+f"(acc[mi][ni][2]), "+f"(acc[mi][ni][3])
                        : "r"(aF[mi][0]), "r"(aF[mi][1]), "r"(aF[mi][2]), "r"(aF[mi][3]),
                          "r"(bF[ni][0]), "r"(bF[ni][1]));
                }
        }
        __syncthreads();   // protect stage before next-next load overwrites it
    }

    // ------- epilogue: scale by ts*scale[o], add bias -------
    const float ts = tscales[*step];
#pragma unroll
    for (int ni = 0; ni < 8; ni++) {
        int gn = bn0 + warpN * 64 + ni * 8 + (lane & 3) * 2;
        float s0 = wscale[gn]     * ts;
        float s1 = wscale[gn + 1] * ts;
        float b0 = bias[gn];
        float b1 = bias[gn + 1];
#pragma unroll
        for (int mi = 0; mi < 2; mi++) {
            int gm = bm0 + warpM * 32 + mi * 16 + (lane >> 2);
            float2 r01;
            r01.x = acc[mi][ni][0] * s0 + b0;
            r01.y = acc[mi][ni][1] * s1 + b1;
            *reinterpret_cast<float2*>(&out[(size_t)gm * NDIM + gn]) = r01;
            float2 r23;
            r23.x = acc[mi][ni][2] * s0 + b0;
            r23.y = acc[mi][ni][3] * s1 + b1;
            *reinterpret_cast<float2*>(&out[(size_t)(gm + 8) * NDIM + gn]) = r23;
        }
    }
}

// ---------------------------------------------------------------------------
// launch
// inputs: 0=x 1=pretrained_weight 2=lora_A 3=lora_B 4=weight_scale
//         5=temporal_scales 6=bias 7=current_step
// ---------------------------------------------------------------------------
extern "C" void kernel_launch(void* const* d_in, const int* in_sizes, int n_in,
                              void* d_out, int out_size) {
    const float* x   = (const float*)d_in[0];
    const float* W   = (const float*)d_in[1];
    const float* lA  = (const float*)d_in[2];
    const float* lB  = (const float*)d_in[3];
    const float* ws  = (const float*)d_in[4];
    const float* tsc = (const float*)d_in[5];
    const float* bia = (const float*)d_in[6];
    const int*   stp = (const int*)  d_in[7];
    float* out = (float*)d_out;

    {   // activation quant: 33.5M elems / 4 per thread
        int n4 = (MTOT * KDIM) / 4;
        int threads = 256;
        int blocks = (n4 + threads - 1) / threads;
        quant_x_kernel<<<blocks, threads>>>(x, tsc, stp);
    }
    {   // weight merge+quant: one block per output row
        quant_w_kernel<<<NDIM, 1024>>>(W, lA, lB, ws);
    }
    {   // GEMM
        dim3 grid(NDIM / BN, MTOT / BM);   // (32, 64)
        gemm_kernel<<<grid, 256>>>(out, ws, bia, tsc, stp);
    }
}